// round 5
// baseline (speedup 1.0000x reference)
#include <cuda_runtime.h>
#include <cuda_bf16.h>

// c2 [100,128,64,64] f32 -> pixel (7,7) => elem offset 455, channel stride 4096
// c3 [100,256,32,32] f32 -> pixel (3,3) => elem offset 99,  channel stride 1024
// out = #{ (c2[:,:,7,7] > med1) != mask1 } + #{ (c3[:,:,3,3] > med2) != mask2 }
// (squared diff of {0,1} values == mismatch count; exact integer)

#define B_   100
#define N1_  (B_ * 128)              // 12800 = 25 blocks * 512
#define NT_  (N1_ + B_ * 256)        // 38400 = 75 blocks * 512 (exact)
#define THREADS_ 512
#define BLOCKS_  (NT_ / THREADS_)    // 75
#define BLOCKS1_ (N1_ / THREADS_)    // 25
#define WPB_     (THREADS_ / 32)     // 16 warps per block

// Packed accumulator: high 32 bits = block ticket count, low 32 = mismatch sum.
// Self-resets at end of every launch (graph-replay safe).
__device__ unsigned long long g_acc = 0ull;

__global__ void __launch_bounds__(THREADS_, 1)
dsverifier_kernel(const float* __restrict__ c2,
                  const float* __restrict__ c3,
                  const float* __restrict__ mask1,
                  const float* __restrict__ mask2,
                  const float* __restrict__ median1,
                  const float* __restrict__ median2,
                  float* __restrict__ out)
{
    const int tid = threadIdx.x;
    const int bid = blockIdx.x;
    const int i   = bid * THREADS_ + tid;

    bool diff;
    if (bid < BLOCKS1_) {
        float v  = __ldg(&c2[(size_t)i * 4096 + 455]);
        float mk = __ldg(&mask1[i]);
        float md = __ldg(median1);
        diff = (v > md) != (mk != 0.0f);
    } else {
        const int j = i - N1_;
        float v  = __ldg(&c3[(size_t)j * 1024 + 99]);
        float mk = __ldg(&mask2[j]);
        float md = __ldg(median2);
        diff = (v > md) != (mk != 0.0f);
    }

    // warp count: one ballot + popc (summand is 0/1)
    const unsigned bal  = __ballot_sync(0xFFFFFFFFu, diff);
    const int      lane = tid & 31;
    const int      wid  = tid >> 5;

    __shared__ unsigned wsum[WPB_];
    if (lane == 0) wsum[wid] = (unsigned)__popc(bal);
    __syncthreads();

    // warp 0 reduces the 16 per-warp counts and issues ONE atomic per block
    if (wid == 0) {
        unsigned v = (lane < WPB_) ? wsum[lane] : 0u;
        #pragma unroll
        for (int off = 8; off > 0; off >>= 1)
            v += __shfl_down_sync(0xFFFFFFFFu, v, off);

        if (lane == 0) {
            // Single RMW carries both partial sum and arrival ticket:
            // same-address ordering makes a fence unnecessary.
            unsigned long long prev =
                atomicAdd(&g_acc, ((unsigned long long)1 << 32) | (unsigned long long)v);
            if ((unsigned)(prev >> 32) == (unsigned)(BLOCKS_ - 1)) {
                unsigned total = (unsigned)(prev & 0xFFFFFFFFull) + v;
                *out = (float)total;           // exact (<= 38400 < 2^24)
                atomicExch(&g_acc, 0ull);      // reset for next graph replay
            }
        }
    }
}

extern "C" void kernel_launch(void* const* d_in, const int* in_sizes, int n_in,
                              void* d_out, int out_size)
{
    const float* c2      = (const float*)d_in[0];
    const float* c3      = (const float*)d_in[1];
    const float* mask1   = (const float*)d_in[2];
    const float* mask2   = (const float*)d_in[3];
    const float* median1 = (const float*)d_in[4];
    const float* median2 = (const float*)d_in[5];
    float* out = (float*)d_out;

    dsverifier_kernel<<<BLOCKS_, THREADS_>>>(c2, c3, mask1, mask2,
                                             median1, median2, out);
}

// round 6
// speedup vs baseline: 1.0435x; 1.0435x over previous
#include <cuda_runtime.h>
#include <cuda_bf16.h>

// c2 [100,128,64,64] f32 -> pixel (7,7) => elem offset 455, channel stride 4096
// c3 [100,256,32,32] f32 -> pixel (3,3) => elem offset 99,  channel stride 1024
// out = #{ (c2[:,:,7,7] > med1) != mask1 } + #{ (c3[:,:,3,3] > med2) != mask2 }
// (squared diff of {0,1} values == mismatch count; exact integer)

#define B_      100
#define N1_     (B_ * 128)             // 12800
#define NT_     (N1_ + B_ * 256)       // 38400
#define THREADS_ 128
#define IPT_     4                     // items per thread (float4 mask load)
#define IPB_     (THREADS_ * IPT_)     // 512 items per block
#define BLOCKS_  (NT_ / IPB_)          // 75 (exact)
#define BLOCKS1_ (N1_ / IPB_)          // 25 (exact) -> block-uniform segment split

// Packed accumulator: high 32 bits = warp ticket, low 32 = mismatch sum.
// Self-resets every launch (graph-replay safe).
__device__ unsigned long long g_acc = 0ull;

#define NWARPS_ (BLOCKS_ * THREADS_ / 32)   // 300

__global__ void __launch_bounds__(THREADS_, 1)
dsverifier_kernel(const float* __restrict__ c2,
                  const float* __restrict__ c3,
                  const float* __restrict__ mask1,
                  const float* __restrict__ mask2,
                  const float* __restrict__ median1,
                  const float* __restrict__ median2,
                  float* __restrict__ out)
{
    const int tid  = threadIdx.x;
    const int bid  = blockIdx.x;

    unsigned cnt;
    if (bid < BLOCKS1_) {
        const int base = (bid * THREADS_ + tid) * IPT_;        // first channel idx
        const float  md = __ldg(median1);
        const float4 mk = __ldg((const float4*)(mask1 + base)); // 16B aligned
        // 4 independent gathers, 16 KB apart -> MLP=4
        float v0 = __ldg(&c2[(size_t)(base + 0) * 4096 + 455]);
        float v1 = __ldg(&c2[(size_t)(base + 1) * 4096 + 455]);
        float v2 = __ldg(&c2[(size_t)(base + 2) * 4096 + 455]);
        float v3 = __ldg(&c2[(size_t)(base + 3) * 4096 + 455]);
        cnt  = (unsigned)((v0 > md) != (mk.x != 0.0f));
        cnt += (unsigned)((v1 > md) != (mk.y != 0.0f));
        cnt += (unsigned)((v2 > md) != (mk.z != 0.0f));
        cnt += (unsigned)((v3 > md) != (mk.w != 0.0f));
    } else {
        const int base = ((bid - BLOCKS1_) * THREADS_ + tid) * IPT_;
        const float  md = __ldg(median2);
        const float4 mk = __ldg((const float4*)(mask2 + base));
        float v0 = __ldg(&c3[(size_t)(base + 0) * 1024 + 99]);
        float v1 = __ldg(&c3[(size_t)(base + 1) * 1024 + 99]);
        float v2 = __ldg(&c3[(size_t)(base + 2) * 1024 + 99]);
        float v3 = __ldg(&c3[(size_t)(base + 3) * 1024 + 99]);
        cnt  = (unsigned)((v0 > md) != (mk.x != 0.0f));
        cnt += (unsigned)((v1 > md) != (mk.y != 0.0f));
        cnt += (unsigned)((v2 > md) != (mk.z != 0.0f));
        cnt += (unsigned)((v3 > md) != (mk.w != 0.0f));
    }

    // single-instruction warp reduction (REDUX.SUM)
    const unsigned wtotal = __reduce_add_sync(0xFFFFFFFFu, cnt);

    if ((tid & 31) == 0) {
        // One RMW carries both partial sum and arrival ticket: same-address
        // ordering, so no fence / no syncthreads needed anywhere.
        unsigned long long prev =
            atomicAdd(&g_acc, ((unsigned long long)1 << 32) | (unsigned long long)wtotal);
        if ((unsigned)(prev >> 32) == (unsigned)(NWARPS_ - 1)) {
            unsigned total = (unsigned)(prev & 0xFFFFFFFFull) + wtotal;
            *out = (float)total;            // exact (<= 38400 < 2^24)
            atomicExch(&g_acc, 0ull);       // reset for next graph replay
        }
    }
}

extern "C" void kernel_launch(void* const* d_in, const int* in_sizes, int n_in,
                              void* d_out, int out_size)
{
    const float* c2      = (const float*)d_in[0];
    const float* c3      = (const float*)d_in[1];
    const float* mask1   = (const float*)d_in[2];
    const float* mask2   = (const float*)d_in[3];
    const float* median1 = (const float*)d_in[4];
    const float* median2 = (const float*)d_in[5];
    float* out = (float*)d_out;

    dsverifier_kernel<<<BLOCKS_, THREADS_>>>(c2, c3, mask1, mask2,
                                             median1, median2, out);
}